// round 3
// baseline (speedup 1.0000x reference)
#include <cuda_runtime.h>
#include <cstdint>

// Problem constants (fixed by the dataset)
#define BATCH 2
#define SEQ   512
#define BS    (BATCH * SEQ)      // 1024 tokens
#define FDIM  16384              // n_features
#define DDIM  768                // d_model
#define MCON  262144             // n_connections

// Static device scratch (no allocations allowed in kernel_launch)
__device__ float g_udT[(size_t)FDIM * DDIM];     // up_decoder transposed: [F, D]
__device__ float g_ufT[(size_t)FDIM * BS];       // up_facts transposed:   [F, BS]
__device__ float g_outT[(size_t)FDIM * BS];      // output transposed:     [F, BS]
__device__ float g_values[MCON];                 // per-connection value
__device__ int   g_rowptr[FDIM + 1];             // CSR row pointers over sorted i

// ---------------------------------------------------------------------------
// Tiled 32x32 transpose: src[R, C] -> dst[C, R]
// ---------------------------------------------------------------------------
__global__ void transpose_kernel(const float* __restrict__ src,
                                 float* __restrict__ dst,
                                 int R, int C) {
    __shared__ float tile[32][33];
    int c = blockIdx.x * 32 + threadIdx.x;
    int r = blockIdx.y * 32 + threadIdx.y;
#pragma unroll
    for (int k = 0; k < 32; k += 8) {
        if (r + k < R && c < C)
            tile[threadIdx.y + k][threadIdx.x] = src[(size_t)(r + k) * C + c];
    }
    __syncthreads();
    int c2 = blockIdx.y * 32 + threadIdx.x;  // dst column = src row
    int r2 = blockIdx.x * 32 + threadIdx.y;  // dst row    = src column
#pragma unroll
    for (int k = 0; k < 32; k += 8) {
        if (r2 + k < C && c2 < R)
            dst[(size_t)(r2 + k) * R + c2] = tile[threadIdx.x][threadIdx.y + k];
    }
}

// ---------------------------------------------------------------------------
// Row pointers: g_rowptr[f] = lower_bound(i_indices, f). i_indices is sorted.
// ---------------------------------------------------------------------------
__global__ void rowptr_kernel(const int* __restrict__ i_indices) {
    int f = blockIdx.x * blockDim.x + threadIdx.x;
    if (f > FDIM) return;
    int lo = 0, hi = MCON;
    while (lo < hi) {
        int mid = (lo + hi) >> 1;
        if (i_indices[mid] < f) lo = mid + 1;
        else hi = mid;
    }
    g_rowptr[f] = lo;
}

// ---------------------------------------------------------------------------
// SDDMM values: one warp per i-row. E[i] held in registers (6 x float4/lane,
// coalesced). For each m in group(i): dot(E[i], udT[j_m]) with warp reduce.
// ---------------------------------------------------------------------------
__global__ void values_kernel(const float* __restrict__ down_encoder,
                              const int* __restrict__ j_indices) {
    int warp = (blockIdx.x * blockDim.x + threadIdx.x) >> 5;
    int lane = threadIdx.x & 31;
    if (warp >= FDIM) return;
    const int i = warp;

    const float4* E4 = reinterpret_cast<const float4*>(down_encoder + (size_t)i * DDIM);
    float4 e[6];
#pragma unroll
    for (int k = 0; k < 6; k++) e[k] = E4[k * 32 + lane];

    int m0 = g_rowptr[i];
    int m1 = g_rowptr[i + 1];
    for (int m = m0; m < m1; m++) {
        int j = j_indices[m];
        const float4* U4 = reinterpret_cast<const float4*>(g_udT + (size_t)j * DDIM);
        float s = 0.0f;
#pragma unroll
        for (int k = 0; k < 6; k++) {
            float4 u = U4[k * 32 + lane];
            s += e[k].x * u.x + e[k].y * u.y + e[k].z * u.z + e[k].w * u.w;
        }
#pragma unroll
        for (int off = 16; off; off >>= 1)
            s += __shfl_xor_sync(0xffffffffu, s, off);
        if (lane == 0) g_values[m] = s;
    }
}

// ---------------------------------------------------------------------------
// SpMM: one block per output row i (256 threads, float4 per thread = 1024 cols).
// outT[i, :] = sum_{m in group(i)} values[m] * ufT[j_m, :]
// ---------------------------------------------------------------------------
__global__ void spmm_kernel(const int* __restrict__ j_indices) {
    const int i = blockIdx.x;
    const int t = threadIdx.x;  // 0..255, owns 4 consecutive columns

    int m0 = g_rowptr[i];
    int m1 = g_rowptr[i + 1];

    float4 acc = make_float4(0.f, 0.f, 0.f, 0.f);
    const float4* uf4 = reinterpret_cast<const float4*>(g_ufT);

    int m = m0;
    // 2-way unrolled for load-level parallelism
    for (; m + 1 < m1; m += 2) {
        float v0 = g_values[m];
        float v1 = g_values[m + 1];
        int j0 = j_indices[m];
        int j1 = j_indices[m + 1];
        float4 u0 = uf4[(size_t)j0 * (BS / 4) + t];
        float4 u1 = uf4[(size_t)j1 * (BS / 4) + t];
        acc.x += v0 * u0.x; acc.y += v0 * u0.y; acc.z += v0 * u0.z; acc.w += v0 * u0.w;
        acc.x += v1 * u1.x; acc.y += v1 * u1.y; acc.z += v1 * u1.z; acc.w += v1 * u1.w;
    }
    for (; m < m1; m++) {
        float v = g_values[m];
        int j = j_indices[m];
        float4 u = uf4[(size_t)j * (BS / 4) + t];
        acc.x += v * u.x; acc.y += v * u.y; acc.z += v * u.z; acc.w += v * u.w;
    }

    reinterpret_cast<float4*>(g_outT)[(size_t)i * (BS / 4) + t] = acc;
}

// ---------------------------------------------------------------------------
// Launch: transpose ud -> transpose uf -> rowptr -> values -> spmm -> transpose out
// ---------------------------------------------------------------------------
extern "C" void kernel_launch(void* const* d_in, const int* in_sizes, int n_in,
                              void* d_out, int out_size) {
    const float* up_facts     = (const float*)d_in[0];   // [B, S, F]
    const float* down_encoder = (const float*)d_in[1];   // [F, D]
    const float* up_decoder   = (const float*)d_in[2];   // [D, F]
    const int*   i_indices    = (const int*)d_in[3];     // [M], sorted, int32
    const int*   j_indices    = (const int*)d_in[4];     // [M], int32
    float*       out          = (float*)d_out;           // [B, S, F]

    float* udT;  cudaGetSymbolAddress((void**)&udT,  g_udT);
    float* ufT;  cudaGetSymbolAddress((void**)&ufT,  g_ufT);
    float* outT; cudaGetSymbolAddress((void**)&outT, g_outT);

    dim3 tb(32, 8);

    // 1) up_decoder [D, F] -> udT [F, D]
    {
        dim3 grid(FDIM / 32, DDIM / 32);
        transpose_kernel<<<grid, tb>>>(up_decoder, udT, DDIM, FDIM);
    }
    // 2) up_facts [BS, F] -> ufT [F, BS]
    {
        dim3 grid(FDIM / 32, BS / 32);
        transpose_kernel<<<grid, tb>>>(up_facts, ufT, BS, FDIM);
    }
    // 3) CSR row pointers from sorted i_indices
    {
        int n = FDIM + 1;
        rowptr_kernel<<<(n + 255) / 256, 256>>>(i_indices);
    }
    // 4) SDDMM values (warp per i)
    {
        int warps = FDIM;
        int threads = 256;
        int blocks = (warps * 32 + threads - 1) / threads;
        values_kernel<<<blocks, threads>>>(down_encoder, j_indices);
    }
    // 5) SpMM into outT (block per i)
    {
        spmm_kernel<<<FDIM, 256>>>(j_indices);
    }
    // 6) outT [F, BS] -> out [BS, F]
    {
        dim3 grid(BS / 32, FDIM / 32);
        transpose_kernel<<<grid, tb>>>(outT, out, FDIM, BS);
    }
}

// round 4
// speedup vs baseline: 1.1154x; 1.1154x over previous
#include <cuda_runtime.h>
#include <cstdint>

// Problem constants (fixed by the dataset)
#define BATCH 2
#define SEQ   512
#define BS    (BATCH * SEQ)      // 1024 tokens
#define FDIM  16384              // n_features
#define DDIM  768                // d_model
#define MCON  262144             // n_connections

// SpMM tile
#define TI 32    // i rows per block
#define TT 128   // tokens per block

// Static device scratch (no allocations allowed in kernel_launch)
__device__ float g_udT[(size_t)FDIM * DDIM];     // up_decoder transposed: [F, D]
__device__ float g_ufT[(size_t)FDIM * BS];       // up_facts transposed:   [F, BS]
__device__ float g_values[MCON];                 // per-connection value
__device__ int   g_rowptr[FDIM + 1];             // CSR row pointers over sorted i

// ---------------------------------------------------------------------------
// Tiled 32x32 transpose: src[R, C] -> dst[C, R]
// ---------------------------------------------------------------------------
__global__ void transpose_kernel(const float* __restrict__ src,
                                 float* __restrict__ dst,
                                 int R, int C) {
    __shared__ float tile[32][33];
    int c = blockIdx.x * 32 + threadIdx.x;
    int r = blockIdx.y * 32 + threadIdx.y;
#pragma unroll
    for (int k = 0; k < 32; k += 8) {
        if (r + k < R && c < C)
            tile[threadIdx.y + k][threadIdx.x] = src[(size_t)(r + k) * C + c];
    }
    __syncthreads();
    int c2 = blockIdx.y * 32 + threadIdx.x;  // dst column = src row
    int r2 = blockIdx.x * 32 + threadIdx.y;  // dst row    = src column
#pragma unroll
    for (int k = 0; k < 32; k += 8) {
        if (r2 + k < C && c2 < R)
            dst[(size_t)(r2 + k) * R + c2] = tile[threadIdx.x][threadIdx.y + k];
    }
}

// ---------------------------------------------------------------------------
// Row pointers: g_rowptr[f] = lower_bound(i_indices, f). i_indices is sorted.
// ---------------------------------------------------------------------------
__global__ void rowptr_kernel(const int* __restrict__ i_indices) {
    int f = blockIdx.x * blockDim.x + threadIdx.x;
    if (f > FDIM) return;
    int lo = 0, hi = MCON;
    while (lo < hi) {
        int mid = (lo + hi) >> 1;
        if (i_indices[mid] < f) lo = mid + 1;
        else hi = mid;
    }
    g_rowptr[f] = lo;
}

// ---------------------------------------------------------------------------
// SDDMM values: one warp per i-row, 2-way unroll over m for MLP.
// E[i] held in registers (6 x float4/lane, coalesced).
// ---------------------------------------------------------------------------
__global__ void values_kernel(const float* __restrict__ down_encoder,
                              const int* __restrict__ j_indices) {
    int warp = (blockIdx.x * blockDim.x + threadIdx.x) >> 5;
    int lane = threadIdx.x & 31;
    if (warp >= FDIM) return;
    const int i = warp;

    const float4* E4 = reinterpret_cast<const float4*>(down_encoder + (size_t)i * DDIM);
    float4 e[6];
#pragma unroll
    for (int k = 0; k < 6; k++) e[k] = E4[k * 32 + lane];

    int m0 = g_rowptr[i];
    int m1 = g_rowptr[i + 1];

    int m = m0;
    for (; m + 1 < m1; m += 2) {
        int j0 = __ldg(&j_indices[m]);
        int j1 = __ldg(&j_indices[m + 1]);
        const float4* U0 = reinterpret_cast<const float4*>(g_udT + (size_t)j0 * DDIM);
        const float4* U1 = reinterpret_cast<const float4*>(g_udT + (size_t)j1 * DDIM);
        float s0 = 0.0f, s1 = 0.0f;
#pragma unroll
        for (int k = 0; k < 6; k++) {
            float4 u0 = U0[k * 32 + lane];
            float4 u1 = U1[k * 32 + lane];
            s0 += e[k].x * u0.x + e[k].y * u0.y + e[k].z * u0.z + e[k].w * u0.w;
            s1 += e[k].x * u1.x + e[k].y * u1.y + e[k].z * u1.z + e[k].w * u1.w;
        }
#pragma unroll
        for (int off = 16; off; off >>= 1) {
            s0 += __shfl_xor_sync(0xffffffffu, s0, off);
            s1 += __shfl_xor_sync(0xffffffffu, s1, off);
        }
        if (lane == 0) {
            g_values[m]     = s0;
            g_values[m + 1] = s1;
        }
    }
    for (; m < m1; m++) {
        int j = __ldg(&j_indices[m]);
        const float4* U4 = reinterpret_cast<const float4*>(g_udT + (size_t)j * DDIM);
        float s = 0.0f;
#pragma unroll
        for (int k = 0; k < 6; k++) {
            float4 u = U4[k * 32 + lane];
            s += e[k].x * u.x + e[k].y * u.y + e[k].z * u.z + e[k].w * u.w;
        }
#pragma unroll
        for (int off = 16; off; off >>= 1)
            s += __shfl_xor_sync(0xffffffffu, s, off);
        if (lane == 0) g_values[m] = s;
    }
}

// ---------------------------------------------------------------------------
// Fused SpMM + output transpose.
// Block computes a [TI=32 i-rows] x [TT=128 tokens] output tile.
// Each warp handles 4 i-rows (one at a time); lane owns 4 consecutive tokens.
// Result staged in smem, then written to out[token][i] in coalesced 128B rows.
// ---------------------------------------------------------------------------
__global__ void spmm_fused_kernel(const int* __restrict__ j_indices,
                                  float* __restrict__ out) {
    __shared__ float tile[TI][TT + 1];   // +1 pad: conflict-free col reads

    const int i_base = blockIdx.x * TI;
    const int tok0   = blockIdx.y * TT;
    const int warp   = threadIdx.x >> 5;
    const int lane   = threadIdx.x & 31;

    const float4* uf4 = reinterpret_cast<const float4*>(g_ufT);
    const int tcol = (tok0 >> 2) + lane;   // float4 index into a ufT row

    for (int ii = warp; ii < TI; ii += 8) {
        const int i = i_base + ii;
        int m0 = g_rowptr[i];
        int m1 = g_rowptr[i + 1];

        float4 acc = make_float4(0.f, 0.f, 0.f, 0.f);

        int m = m0;
        for (; m + 3 < m1; m += 4) {
            float v0 = g_values[m];
            float v1 = g_values[m + 1];
            float v2 = g_values[m + 2];
            float v3 = g_values[m + 3];
            int j0 = __ldg(&j_indices[m]);
            int j1 = __ldg(&j_indices[m + 1]);
            int j2 = __ldg(&j_indices[m + 2]);
            int j3 = __ldg(&j_indices[m + 3]);
            float4 u0 = uf4[(size_t)j0 * (BS / 4) + tcol];
            float4 u1 = uf4[(size_t)j1 * (BS / 4) + tcol];
            float4 u2 = uf4[(size_t)j2 * (BS / 4) + tcol];
            float4 u3 = uf4[(size_t)j3 * (BS / 4) + tcol];
            acc.x += v0 * u0.x; acc.y += v0 * u0.y; acc.z += v0 * u0.z; acc.w += v0 * u0.w;
            acc.x += v1 * u1.x; acc.y += v1 * u1.y; acc.z += v1 * u1.z; acc.w += v1 * u1.w;
            acc.x += v2 * u2.x; acc.y += v2 * u2.y; acc.z += v2 * u2.z; acc.w += v2 * u2.w;
            acc.x += v3 * u3.x; acc.y += v3 * u3.y; acc.z += v3 * u3.z; acc.w += v3 * u3.w;
        }
        for (; m < m1; m++) {
            float v = g_values[m];
            int j = __ldg(&j_indices[m]);
            float4 u = uf4[(size_t)j * (BS / 4) + tcol];
            acc.x += v * u.x; acc.y += v * u.y; acc.z += v * u.z; acc.w += v * u.w;
        }

        // Scalar stores into padded smem row (stride TT+1 keeps writes/readouts clean)
        tile[ii][lane * 4 + 0] = acc.x;
        tile[ii][lane * 4 + 1] = acc.y;
        tile[ii][lane * 4 + 2] = acc.z;
        tile[ii][lane * 4 + 3] = acc.w;
    }
    __syncthreads();

    // Write out: each warp writes one token row (32 consecutive i's = 128B)
    for (int t = warp; t < TT; t += 8) {
        out[(size_t)(tok0 + t) * FDIM + i_base + lane] = tile[lane][t];
    }
}

// ---------------------------------------------------------------------------
// Launch sequence
// ---------------------------------------------------------------------------
extern "C" void kernel_launch(void* const* d_in, const int* in_sizes, int n_in,
                              void* d_out, int out_size) {
    const float* up_facts     = (const float*)d_in[0];   // [B, S, F]
    const float* down_encoder = (const float*)d_in[1];   // [F, D]
    const float* up_decoder   = (const float*)d_in[2];   // [D, F]
    const int*   i_indices    = (const int*)d_in[3];     // [M], sorted, int32
    const int*   j_indices    = (const int*)d_in[4];     // [M], int32
    float*       out          = (float*)d_out;           // [B, S, F]

    float* udT;  cudaGetSymbolAddress((void**)&udT,  g_udT);
    float* ufT;  cudaGetSymbolAddress((void**)&ufT,  g_ufT);

    dim3 tb(32, 8);

    // 1) up_decoder [D, F] -> udT [F, D]
    {
        dim3 grid(FDIM / 32, DDIM / 32);
        transpose_kernel<<<grid, tb>>>(up_decoder, udT, DDIM, FDIM);
    }
    // 2) up_facts [BS, F] -> ufT [F, BS]
    {
        dim3 grid(FDIM / 32, BS / 32);
        transpose_kernel<<<grid, tb>>>(up_facts, ufT, BS, FDIM);
    }
    // 3) CSR row pointers from sorted i_indices
    {
        int n = FDIM + 1;
        rowptr_kernel<<<(n + 255) / 256, 256>>>(i_indices);
    }
    // 4) SDDMM values (warp per i, 2-way m unroll)
    {
        int threads = 256;
        int blocks = (FDIM * 32 + threads - 1) / threads;
        values_kernel<<<blocks, threads>>>(down_encoder, j_indices);
    }
    // 5) Fused SpMM + output transpose
    {
        dim3 grid(FDIM / TI, BS / TT);
        spmm_fused_kernel<<<grid, 256>>>(j_indices, out);
    }
}

// round 5
// speedup vs baseline: 1.3569x; 1.2165x over previous
#include <cuda_runtime.h>
#include <cuda_fp16.h>
#include <cstdint>

// Problem constants (fixed by the dataset)
#define BATCH 2
#define SEQ   512
#define BS    (BATCH * SEQ)      // 1024 tokens
#define FDIM  16384              // n_features
#define DDIM  768                // d_model
#define MCON  262144             // n_connections

// SpMM tile
#define TI 32    // i rows per block
#define TT 256   // tokens per block (lane owns 8 via one uint4 of halves)

// Static device scratch (no allocations allowed in kernel_launch)
__device__ __half g_udT[(size_t)FDIM * DDIM];    // up_decoder transposed: [F, D], fp16
__device__ __half g_ufT[(size_t)FDIM * BS];      // up_facts transposed:   [F, BS], fp16
__device__ float  g_values[MCON];                // per-connection value (fp32)
__device__ int    g_rowptr[FDIM + 1];            // CSR row pointers over sorted i

// ---------------------------------------------------------------------------
// Tiled 32x32 transpose with fp32 -> fp16 convert: src[R, C] -> dst[C, R]
// ---------------------------------------------------------------------------
__global__ void transpose_f2h_kernel(const float* __restrict__ src,
                                     __half* __restrict__ dst,
                                     int R, int C) {
    __shared__ float tile[32][33];
    int c = blockIdx.x * 32 + threadIdx.x;
    int r = blockIdx.y * 32 + threadIdx.y;
#pragma unroll
    for (int k = 0; k < 32; k += 8) {
        if (r + k < R && c < C)
            tile[threadIdx.y + k][threadIdx.x] = src[(size_t)(r + k) * C + c];
    }
    __syncthreads();
    int c2 = blockIdx.y * 32 + threadIdx.x;  // dst column = src row
    int r2 = blockIdx.x * 32 + threadIdx.y;  // dst row    = src column
#pragma unroll
    for (int k = 0; k < 32; k += 8) {
        if (r2 + k < C && c2 < R)
            dst[(size_t)(r2 + k) * R + c2] = __float2half_rn(tile[threadIdx.x][threadIdx.y + k]);
    }
}

// ---------------------------------------------------------------------------
// Row pointers: g_rowptr[f] = lower_bound(i_indices, f). i_indices is sorted.
// ---------------------------------------------------------------------------
__global__ void rowptr_kernel(const int* __restrict__ i_indices) {
    int f = blockIdx.x * blockDim.x + threadIdx.x;
    if (f > FDIM) return;
    int lo = 0, hi = MCON;
    while (lo < hi) {
        int mid = (lo + hi) >> 1;
        if (i_indices[mid] < f) lo = mid + 1;
        else hi = mid;
    }
    g_rowptr[f] = lo;
}

// ---------------------------------------------------------------------------
// SDDMM values: TWO warps per i-row (even/odd m split) for latency hiding.
// E[i] held fp32 in registers, layout-matched to the fp16 U row loads.
// Lane owns D-elements [(k*32+lane)*8 .. +8) for k = 0..2 (24 elems).
// ---------------------------------------------------------------------------
__global__ void values_kernel(const float* __restrict__ down_encoder,
                              const int* __restrict__ j_indices) {
    int gwarp = (blockIdx.x * blockDim.x + threadIdx.x) >> 5;
    int lane = threadIdx.x & 31;
    if (gwarp >= FDIM * 2) return;
    const int i      = gwarp >> 1;
    const int parity = gwarp & 1;

    // Load E[i] in pairs of float4 matching the uint4-of-8-halves layout.
    const float4* E4 = reinterpret_cast<const float4*>(down_encoder + (size_t)i * DDIM);
    float4 ea[3], eb[3];
#pragma unroll
    for (int k = 0; k < 3; k++) {
        int base = 2 * (k * 32 + lane);
        ea[k] = E4[base];
        eb[k] = E4[base + 1];
    }

    int m1 = g_rowptr[i + 1];
    for (int m = g_rowptr[i] + parity; m < m1; m += 2) {
        int j = __ldg(&j_indices[m]);
        const uint4* U = reinterpret_cast<const uint4*>(g_udT + (size_t)j * DDIM);
        float s = 0.0f;
#pragma unroll
        for (int k = 0; k < 3; k++) {
            uint4 u = U[k * 32 + lane];
            float2 f0 = __half22float2(*reinterpret_cast<__half2*>(&u.x));
            float2 f1 = __half22float2(*reinterpret_cast<__half2*>(&u.y));
            float2 f2 = __half22float2(*reinterpret_cast<__half2*>(&u.z));
            float2 f3 = __half22float2(*reinterpret_cast<__half2*>(&u.w));
            s += ea[k].x * f0.x + ea[k].y * f0.y + ea[k].z * f1.x + ea[k].w * f1.y;
            s += eb[k].x * f2.x + eb[k].y * f2.y + eb[k].z * f3.x + eb[k].w * f3.y;
        }
#pragma unroll
        for (int off = 16; off; off >>= 1)
            s += __shfl_xor_sync(0xffffffffu, s, off);
        if (lane == 0) g_values[m] = s;
    }
}

// ---------------------------------------------------------------------------
// Fused SpMM + output transpose, fp16 activations, fp32 accumulate.
// Block computes [TI=32 i-rows] x [TT=256 tokens]. Warp handles 4 i-rows;
// lane owns 8 consecutive tokens (one uint4 of halves per m).
// Staged in smem, written to out[token][i] as coalesced 128B rows.
// ---------------------------------------------------------------------------
__global__ void spmm_fused_kernel(const int* __restrict__ j_indices,
                                  float* __restrict__ out) {
    __shared__ float tile[TI][TT + 1];   // pad 1: conflict-free column reads

    const int i_base = blockIdx.x * TI;
    const int tok0   = blockIdx.y * TT;
    const int warp   = threadIdx.x >> 5;
    const int lane   = threadIdx.x & 31;

    const uint4* uf = reinterpret_cast<const uint4*>(g_ufT);
    const int tcol = (tok0 >> 3) + lane;   // uint4 index into a ufT row (BS/8 per row)

    for (int ii = warp; ii < TI; ii += 8) {
        const int i = i_base + ii;
        int m0 = g_rowptr[i];
        int m1 = g_rowptr[i + 1];

        float acc[8];
#pragma unroll
        for (int t = 0; t < 8; t++) acc[t] = 0.0f;

        int m = m0;
        for (; m + 1 < m1; m += 2) {
            float v0 = g_values[m];
            float v1 = g_values[m + 1];
            int j0 = __ldg(&j_indices[m]);
            int j1 = __ldg(&j_indices[m + 1]);
            uint4 u0 = uf[(size_t)j0 * (BS / 8) + tcol];
            uint4 u1 = uf[(size_t)j1 * (BS / 8) + tcol];
            {
                float2 f0 = __half22float2(*reinterpret_cast<__half2*>(&u0.x));
                float2 f1 = __half22float2(*reinterpret_cast<__half2*>(&u0.y));
                float2 f2 = __half22float2(*reinterpret_cast<__half2*>(&u0.z));
                float2 f3 = __half22float2(*reinterpret_cast<__half2*>(&u0.w));
                acc[0] += v0 * f0.x; acc[1] += v0 * f0.y;
                acc[2] += v0 * f1.x; acc[3] += v0 * f1.y;
                acc[4] += v0 * f2.x; acc[5] += v0 * f2.y;
                acc[6] += v0 * f3.x; acc[7] += v0 * f3.y;
            }
            {
                float2 f0 = __half22float2(*reinterpret_cast<__half2*>(&u1.x));
                float2 f1 = __half22float2(*reinterpret_cast<__half2*>(&u1.y));
                float2 f2 = __half22float2(*reinterpret_cast<__half2*>(&u1.z));
                float2 f3 = __half22float2(*reinterpret_cast<__half2*>(&u1.w));
                acc[0] += v1 * f0.x; acc[1] += v1 * f0.y;
                acc[2] += v1 * f1.x; acc[3] += v1 * f1.y;
                acc[4] += v1 * f2.x; acc[5] += v1 * f2.y;
                acc[6] += v1 * f3.x; acc[7] += v1 * f3.y;
            }
        }
        for (; m < m1; m++) {
            float v = g_values[m];
            int j = __ldg(&j_indices[m]);
            uint4 u = uf[(size_t)j * (BS / 8) + tcol];
            float2 f0 = __half22float2(*reinterpret_cast<__half2*>(&u.x));
            float2 f1 = __half22float2(*reinterpret_cast<__half2*>(&u.y));
            float2 f2 = __half22float2(*reinterpret_cast<__half2*>(&u.z));
            float2 f3 = __half22float2(*reinterpret_cast<__half2*>(&u.w));
            acc[0] += v * f0.x; acc[1] += v * f0.y;
            acc[2] += v * f1.x; acc[3] += v * f1.y;
            acc[4] += v * f2.x; acc[5] += v * f2.y;
            acc[6] += v * f3.x; acc[7] += v * f3.y;
        }

#pragma unroll
        for (int t = 0; t < 8; t++)
            tile[ii][lane * 8 + t] = acc[t];
    }
    __syncthreads();

    // Write out: warp writes one token row per iter (32 consecutive i's = 128B)
    for (int t = warp; t < TT; t += 8) {
        out[(size_t)(tok0 + t) * FDIM + i_base + lane] = tile[lane][t];
    }
}

// ---------------------------------------------------------------------------
// Launch sequence
// ---------------------------------------------------------------------------
extern "C" void kernel_launch(void* const* d_in, const int* in_sizes, int n_in,
                              void* d_out, int out_size) {
    const float* up_facts     = (const float*)d_in[0];   // [B, S, F]
    const float* down_encoder = (const float*)d_in[1];   // [F, D]
    const float* up_decoder   = (const float*)d_in[2];   // [D, F]
    const int*   i_indices    = (const int*)d_in[3];     // [M], sorted, int32
    const int*   j_indices    = (const int*)d_in[4];     // [M], int32
    float*       out          = (float*)d_out;           // [B, S, F]

    __half* udT; cudaGetSymbolAddress((void**)&udT, g_udT);
    __half* ufT; cudaGetSymbolAddress((void**)&ufT, g_ufT);

    dim3 tb(32, 8);

    // 1) up_decoder [D, F] -> udT [F, D] (fp16)
    {
        dim3 grid(FDIM / 32, DDIM / 32);
        transpose_f2h_kernel<<<grid, tb>>>(up_decoder, udT, DDIM, FDIM);
    }
    // 2) up_facts [BS, F] -> ufT [F, BS] (fp16)
    {
        dim3 grid(FDIM / 32, BS / 32);
        transpose_f2h_kernel<<<grid, tb>>>(up_facts, ufT, BS, FDIM);
    }
    // 3) CSR row pointers from sorted i_indices
    {
        int n = FDIM + 1;
        rowptr_kernel<<<(n + 255) / 256, 256>>>(i_indices);
    }
    // 4) SDDMM values (2 warps per i)
    {
        int threads = 256;
        long long total_threads = (long long)FDIM * 2 * 32;
        int blocks = (int)((total_threads + threads - 1) / threads);
        values_kernel<<<blocks, threads>>>(down_encoder, j_indices);
    }
    // 5) Fused SpMM + output transpose
    {
        dim3 grid(FDIM / TI, BS / TT);
        spmm_fused_kernel<<<grid, 256>>>(j_indices, out);
    }
}

// round 6
// speedup vs baseline: 1.3931x; 1.0267x over previous
#include <cuda_runtime.h>
#include <cuda_fp16.h>
#include <cstdint>

// Problem constants (fixed by the dataset)
#define BATCH 2
#define SEQ   512
#define BS    (BATCH * SEQ)      // 1024 tokens
#define FDIM  16384              // n_features
#define DDIM  768                // d_model
#define MCON  262144             // n_connections

// SpMM tile
#define TI 32    // i rows per block
#define TT 256   // tokens per block (lane owns 8 via one uint4 of halves)

// Static device scratch (no allocations allowed in kernel_launch)
__device__ __half g_udT[(size_t)FDIM * DDIM];    // up_decoder transposed: [F, D], fp16
__device__ __half g_ufT[(size_t)FDIM * BS];      // up_facts transposed:   [F, BS], fp16
__device__ float  g_values[MCON];                // per-connection value (fp32)
__device__ int    g_rowptr[FDIM + 1];            // CSR row pointers over sorted i

// ---------------------------------------------------------------------------
// Tiled 64x32 transpose with fp32 -> fp16 convert and half2 stores.
// src[R, C] fp32 -> dst[C, R] fp16.  Tile: 64 src rows x 32 src cols.
// Write phase: each lane emits one __half2 (two consecutive dst columns
// = two consecutive src rows) -> full-width 128B store transactions.
// Requires R % 64 == 0, C % 32 == 0 (true for all three uses).
// ---------------------------------------------------------------------------
__global__ void transpose_f2h_kernel(const float* __restrict__ src,
                                     __half* __restrict__ dst,
                                     int R, int C) {
    __shared__ float tile[64][33];
    const int x = threadIdx.x;        // 0..31
    const int y = threadIdx.y;        // 0..7
    const int c0 = blockIdx.x * 32;
    const int r0 = blockIdx.y * 64;

#pragma unroll
    for (int k = 0; k < 64; k += 8) {
        tile[y + k][x] = src[(size_t)(r0 + y + k) * C + c0 + x];
    }
    __syncthreads();

    __half2* dst2 = reinterpret_cast<__half2*>(dst);
    const int rhalf = R >> 1;
#pragma unroll
    for (int dr = 0; dr < 32; dr += 8) {
        int row = dr + y;             // src col / dst row within tile
        __half2 v = __floats2half2_rn(tile[2 * x][row], tile[2 * x + 1][row]);
        dst2[(size_t)(c0 + row) * rhalf + (r0 >> 1) + x] = v;
    }
}

// ---------------------------------------------------------------------------
// Row pointers: g_rowptr[f] = lower_bound(i_indices, f). i_indices is sorted.
// ---------------------------------------------------------------------------
__global__ void rowptr_kernel(const int* __restrict__ i_indices) {
    int f = blockIdx.x * blockDim.x + threadIdx.x;
    if (f > FDIM) return;
    int lo = 0, hi = MCON;
    while (lo < hi) {
        int mid = (lo + hi) >> 1;
        if (i_indices[mid] < f) lo = mid + 1;
        else hi = mid;
    }
    g_rowptr[f] = lo;
}

// ---------------------------------------------------------------------------
// SDDMM values: FOUR warps per i-row (m stride 4 by warp parity).
// The 4 warps of one i live in the same block -> E row hits L1 after the
// first warp touches it. E held fp32 in registers, layout-matched to the
// fp16 U row loads (uint4 of 8 halves per lane per k).
// ---------------------------------------------------------------------------
__global__ void values_kernel(const float* __restrict__ down_encoder,
                              const int* __restrict__ j_indices) {
    int gwarp = (blockIdx.x * blockDim.x + threadIdx.x) >> 5;
    int lane = threadIdx.x & 31;
    if (gwarp >= FDIM * 4) return;
    const int i      = gwarp >> 2;
    const int parity = gwarp & 3;

    // Load E[i] in pairs of float4 matching the uint4-of-8-halves layout.
    const float4* E4 = reinterpret_cast<const float4*>(down_encoder + (size_t)i * DDIM);
    float4 ea[3], eb[3];
#pragma unroll
    for (int k = 0; k < 3; k++) {
        int base = 2 * (k * 32 + lane);
        ea[k] = E4[base];
        eb[k] = E4[base + 1];
    }

    int m1 = g_rowptr[i + 1];
    for (int m = g_rowptr[i] + parity; m < m1; m += 4) {
        int j = __ldg(&j_indices[m]);
        const uint4* U = reinterpret_cast<const uint4*>(g_udT + (size_t)j * DDIM);
        float s = 0.0f;
#pragma unroll
        for (int k = 0; k < 3; k++) {
            uint4 u = U[k * 32 + lane];
            float2 f0 = __half22float2(*reinterpret_cast<__half2*>(&u.x));
            float2 f1 = __half22float2(*reinterpret_cast<__half2*>(&u.y));
            float2 f2 = __half22float2(*reinterpret_cast<__half2*>(&u.z));
            float2 f3 = __half22float2(*reinterpret_cast<__half2*>(&u.w));
            s += ea[k].x * f0.x + ea[k].y * f0.y + ea[k].z * f1.x + ea[k].w * f1.y;
            s += eb[k].x * f2.x + eb[k].y * f2.y + eb[k].z * f3.x + eb[k].w * f3.y;
        }
#pragma unroll
        for (int off = 16; off; off >>= 1)
            s += __shfl_xor_sync(0xffffffffu, s, off);
        if (lane == 0) g_values[m] = s;
    }
}

// ---------------------------------------------------------------------------
// Fused SpMM + output transpose, fp16 activations, fp32 accumulate.
// Block computes [TI=32 i-rows] x [TT=256 tokens]. Warp handles 4 i-rows;
// lane owns 8 consecutive tokens (one uint4 of halves per m).
// Staged in smem, written to out[token][i] as coalesced 128B rows.
// ---------------------------------------------------------------------------
__global__ void spmm_fused_kernel(const int* __restrict__ j_indices,
                                  float* __restrict__ out) {
    __shared__ float tile[TI][TT + 1];   // pad 1: conflict-free column reads

    const int i_base = blockIdx.x * TI;
    const int tok0   = blockIdx.y * TT;
    const int warp   = threadIdx.x >> 5;
    const int lane   = threadIdx.x & 31;

    const uint4* uf = reinterpret_cast<const uint4*>(g_ufT);
    const int tcol = (tok0 >> 3) + lane;   // uint4 index into a ufT row (BS/8 per row)

    for (int ii = warp; ii < TI; ii += 8) {
        const int i = i_base + ii;
        int m0 = g_rowptr[i];
        int m1 = g_rowptr[i + 1];

        float acc[8];
#pragma unroll
        for (int t = 0; t < 8; t++) acc[t] = 0.0f;

        int m = m0;
        for (; m + 1 < m1; m += 2) {
            float v0 = g_values[m];
            float v1 = g_values[m + 1];
            int j0 = __ldg(&j_indices[m]);
            int j1 = __ldg(&j_indices[m + 1]);
            uint4 u0 = uf[(size_t)j0 * (BS / 8) + tcol];
            uint4 u1 = uf[(size_t)j1 * (BS / 8) + tcol];
            {
                float2 f0 = __half22float2(*reinterpret_cast<__half2*>(&u0.x));
                float2 f1 = __half22float2(*reinterpret_cast<__half2*>(&u0.y));
                float2 f2 = __half22float2(*reinterpret_cast<__half2*>(&u0.z));
                float2 f3 = __half22float2(*reinterpret_cast<__half2*>(&u0.w));
                acc[0] += v0 * f0.x; acc[1] += v0 * f0.y;
                acc[2] += v0 * f1.x; acc[3] += v0 * f1.y;
                acc[4] += v0 * f2.x; acc[5] += v0 * f2.y;
                acc[6] += v0 * f3.x; acc[7] += v0 * f3.y;
            }
            {
                float2 f0 = __half22float2(*reinterpret_cast<__half2*>(&u1.x));
                float2 f1 = __half22float2(*reinterpret_cast<__half2*>(&u1.y));
                float2 f2 = __half22float2(*reinterpret_cast<__half2*>(&u1.z));
                float2 f3 = __half22float2(*reinterpret_cast<__half2*>(&u1.w));
                acc[0] += v1 * f0.x; acc[1] += v1 * f0.y;
                acc[2] += v1 * f1.x; acc[3] += v1 * f1.y;
                acc[4] += v1 * f2.x; acc[5] += v1 * f2.y;
                acc[6] += v1 * f3.x; acc[7] += v1 * f3.y;
            }
        }
        for (; m < m1; m++) {
            float v = g_values[m];
            int j = __ldg(&j_indices[m]);
            uint4 u = uf[(size_t)j * (BS / 8) + tcol];
            float2 f0 = __half22float2(*reinterpret_cast<__half2*>(&u.x));
            float2 f1 = __half22float2(*reinterpret_cast<__half2*>(&u.y));
            float2 f2 = __half22float2(*reinterpret_cast<__half2*>(&u.z));
            float2 f3 = __half22float2(*reinterpret_cast<__half2*>(&u.w));
            acc[0] += v * f0.x; acc[1] += v * f0.y;
            acc[2] += v * f1.x; acc[3] += v * f1.y;
            acc[4] += v * f2.x; acc[5] += v * f2.y;
            acc[6] += v * f3.x; acc[7] += v * f3.y;
        }

#pragma unroll
        for (int t = 0; t < 8; t++)
            tile[ii][lane * 8 + t] = acc[t];
    }
    __syncthreads();

    // Write out: warp writes one token row per iter (32 consecutive i's = 128B)
    for (int t = warp; t < TT; t += 8) {
        out[(size_t)(tok0 + t) * FDIM + i_base + lane] = tile[lane][t];
    }
}

// ---------------------------------------------------------------------------
// Launch sequence
// ---------------------------------------------------------------------------
extern "C" void kernel_launch(void* const* d_in, const int* in_sizes, int n_in,
                              void* d_out, int out_size) {
    const float* up_facts     = (const float*)d_in[0];   // [B, S, F]
    const float* down_encoder = (const float*)d_in[1];   // [F, D]
    const float* up_decoder   = (const float*)d_in[2];   // [D, F]
    const int*   i_indices    = (const int*)d_in[3];     // [M], sorted, int32
    const int*   j_indices    = (const int*)d_in[4];     // [M], int32
    float*       out          = (float*)d_out;           // [B, S, F]

    __half* udT; cudaGetSymbolAddress((void**)&udT, g_udT);
    __half* ufT; cudaGetSymbolAddress((void**)&ufT, g_ufT);

    dim3 tb(32, 8);

    // 1) up_decoder [D, F] -> udT [F, D] (fp16)  (R=768, 768/64=12)
    {
        dim3 grid(FDIM / 32, DDIM / 64);
        transpose_f2h_kernel<<<grid, tb>>>(up_decoder, udT, DDIM, FDIM);
    }
    // 2) up_facts [BS, F] -> ufT [F, BS] (fp16)  (R=1024, 1024/64=16)
    {
        dim3 grid(FDIM / 32, BS / 64);
        transpose_f2h_kernel<<<grid, tb>>>(up_facts, ufT, BS, FDIM);
    }
    // 3) CSR row pointers from sorted i_indices
    {
        int n = FDIM + 1;
        rowptr_kernel<<<(n + 255) / 256, 256>>>(i_indices);
    }
    // 4) SDDMM values (4 warps per i)
    {
        int threads = 256;
        long long total_threads = (long long)FDIM * 4 * 32;
        int blocks = (int)((total_threads + threads - 1) / threads);
        values_kernel<<<blocks, threads>>>(down_encoder, j_indices);
    }
    // 5) Fused SpMM + output transpose
    {
        dim3 grid(FDIM / TI, BS / TT);
        spmm_fused_kernel<<<grid, 256>>>(j_indices, out);
    }
}

// round 7
// speedup vs baseline: 1.4858x; 1.0665x over previous
#include <cuda_runtime.h>
#include <cuda_fp16.h>
#include <cstdint>

// Problem constants (fixed by the dataset)
#define BATCH 2
#define SEQ   512
#define BS    (BATCH * SEQ)      // 1024 tokens
#define FDIM  16384              // n_features
#define DDIM  768                // d_model
#define MCON  262144             // n_connections

// SpMM tile
#define TI 32    // i rows per block
#define TT 256   // tokens per block (lane owns 8 via one uint4 of halves)

// Prep-kernel grid decomposition
#define T1_BLOCKS ((FDIM / 32) * (DDIM / 64))   // 6144 up_decoder tiles
#define T2_BLOCKS ((FDIM / 32) * (BS / 64))     // 8192 up_facts tiles
#define RP_BLOCKS (((FDIM + 1) + 255) / 256)    // 65 rowptr blocks

// Static device scratch (no allocations allowed in kernel_launch)
__device__ __half g_udT[(size_t)FDIM * DDIM];    // up_decoder transposed: [F, D], fp16
__device__ __half g_ufT[(size_t)FDIM * BS];      // up_facts transposed:   [F, BS], fp16
__device__ float  g_values[MCON];                // per-connection value (fp32)
__device__ int    g_rowptr[FDIM + 1];            // CSR row pointers over sorted i

// ---------------------------------------------------------------------------
// Transpose device helper: 64 src rows x 32 src cols tile, fp32 -> fp16,
// half2-vectorized stores (full-width 128B transactions).
// ---------------------------------------------------------------------------
__device__ __forceinline__ void transpose_tile_f2h(const float* __restrict__ src,
                                                   __half* __restrict__ dst,
                                                   int R, int C, int bx, int by,
                                                   int x, int y) {
    __shared__ float tile[64][33];
    const int c0 = bx * 32;
    const int r0 = by * 64;

#pragma unroll
    for (int k = 0; k < 64; k += 8) {
        tile[y + k][x] = src[(size_t)(r0 + y + k) * C + c0 + x];
    }
    __syncthreads();

    __half2* dst2 = reinterpret_cast<__half2*>(dst);
    const int rhalf = R >> 1;
#pragma unroll
    for (int dr = 0; dr < 32; dr += 8) {
        int row = dr + y;             // src col / dst row within tile
        __half2 v = __floats2half2_rn(tile[2 * x][row], tile[2 * x + 1][row]);
        dst2[(size_t)(c0 + row) * rhalf + (r0 >> 1) + x] = v;
    }
}

// ---------------------------------------------------------------------------
// Merged prep kernel: both transposes + rowptr, branched on block range.
// All three pieces are independent. 256 threads per block.
// ---------------------------------------------------------------------------
__global__ void prep_kernel(const float* __restrict__ up_decoder,
                            const float* __restrict__ up_facts,
                            const int* __restrict__ i_indices,
                            __half* __restrict__ udT,
                            __half* __restrict__ ufT) {
    const int b = blockIdx.x;
    const int x = threadIdx.x & 31;
    const int y = threadIdx.x >> 5;

    if (b < T1_BLOCKS) {
        // up_decoder [DDIM, FDIM] -> udT [FDIM, DDIM]
        int bx = b % (FDIM / 32);
        int by = b / (FDIM / 32);
        transpose_tile_f2h(up_decoder, udT, DDIM, FDIM, bx, by, x, y);
    } else if (b < T1_BLOCKS + T2_BLOCKS) {
        // up_facts [BS, FDIM] -> ufT [FDIM, BS]
        int bb = b - T1_BLOCKS;
        int bx = bb % (FDIM / 32);
        int by = bb / (FDIM / 32);
        transpose_tile_f2h(up_facts, ufT, BS, FDIM, bx, by, x, y);
    } else {
        // rowptr: g_rowptr[f] = lower_bound(i_indices, f)
        int f = (b - T1_BLOCKS - T2_BLOCKS) * 256 + threadIdx.x;
        if (f > FDIM) return;
        int lo = 0, hi = MCON;
        while (lo < hi) {
            int mid = (lo + hi) >> 1;
            if (i_indices[mid] < f) lo = mid + 1;
            else hi = mid;
        }
        g_rowptr[f] = lo;
    }
}

// ---------------------------------------------------------------------------
// SDDMM values: TWO warps per i-row (even/odd m split) for latency hiding.
// E[i] held fp32 in registers, layout-matched to the fp16 U row loads.
// ---------------------------------------------------------------------------
__global__ void values_kernel(const float* __restrict__ down_encoder,
                              const int* __restrict__ j_indices) {
    int gwarp = (blockIdx.x * blockDim.x + threadIdx.x) >> 5;
    int lane = threadIdx.x & 31;
    if (gwarp >= FDIM * 2) return;
    const int i      = gwarp >> 1;
    const int parity = gwarp & 1;

    // Load E[i] in pairs of float4 matching the uint4-of-8-halves layout.
    const float4* E4 = reinterpret_cast<const float4*>(down_encoder + (size_t)i * DDIM);
    float4 ea[3], eb[3];
#pragma unroll
    for (int k = 0; k < 3; k++) {
        int base = 2 * (k * 32 + lane);
        ea[k] = E4[base];
        eb[k] = E4[base + 1];
    }

    int m1 = g_rowptr[i + 1];
    for (int m = g_rowptr[i] + parity; m < m1; m += 2) {
        int j = __ldg(&j_indices[m]);
        const uint4* U = reinterpret_cast<const uint4*>(g_udT + (size_t)j * DDIM);
        float s = 0.0f;
#pragma unroll
        for (int k = 0; k < 3; k++) {
            uint4 u = U[k * 32 + lane];
            float2 f0 = __half22float2(*reinterpret_cast<__half2*>(&u.x));
            float2 f1 = __half22float2(*reinterpret_cast<__half2*>(&u.y));
            float2 f2 = __half22float2(*reinterpret_cast<__half2*>(&u.z));
            float2 f3 = __half22float2(*reinterpret_cast<__half2*>(&u.w));
            s += ea[k].x * f0.x + ea[k].y * f0.y + ea[k].z * f1.x + ea[k].w * f1.y;
            s += eb[k].x * f2.x + eb[k].y * f2.y + eb[k].z * f3.x + eb[k].w * f3.y;
        }
#pragma unroll
        for (int off = 16; off; off >>= 1)
            s += __shfl_xor_sync(0xffffffffu, s, off);
        if (lane == 0) g_values[m] = s;
    }
}

// ---------------------------------------------------------------------------
// Fused SpMM + output transpose, fp16 activations, fp32 accumulate.
// Block computes [TI=32 i-rows] x [TT=256 tokens]. Warp handles 4 i-rows;
// lane owns 8 consecutive tokens (one uint4 of halves per m).
// Staged in smem, written to out[token][i] as coalesced 128B rows.
// ---------------------------------------------------------------------------
__global__ void spmm_fused_kernel(const int* __restrict__ j_indices,
                                  float* __restrict__ out) {
    __shared__ float tile[TI][TT + 1];   // pad 1: conflict-free column reads

    const int i_base = blockIdx.x * TI;
    const int tok0   = blockIdx.y * TT;
    const int warp   = threadIdx.x >> 5;
    const int lane   = threadIdx.x & 31;

    const uint4* uf = reinterpret_cast<const uint4*>(g_ufT);
    const int tcol = (tok0 >> 3) + lane;   // uint4 index into a ufT row (BS/8 per row)

    for (int ii = warp; ii < TI; ii += 8) {
        const int i = i_base + ii;
        int m0 = g_rowptr[i];
        int m1 = g_rowptr[i + 1];

        float acc[8];
#pragma unroll
        for (int t = 0; t < 8; t++) acc[t] = 0.0f;

        int m = m0;
        for (; m + 1 < m1; m += 2) {
            float v0 = g_values[m];
            float v1 = g_values[m + 1];
            int j0 = __ldg(&j_indices[m]);
            int j1 = __ldg(&j_indices[m + 1]);
            uint4 u0 = uf[(size_t)j0 * (BS / 8) + tcol];
            uint4 u1 = uf[(size_t)j1 * (BS / 8) + tcol];
            {
                float2 f0 = __half22float2(*reinterpret_cast<__half2*>(&u0.x));
                float2 f1 = __half22float2(*reinterpret_cast<__half2*>(&u0.y));
                float2 f2 = __half22float2(*reinterpret_cast<__half2*>(&u0.z));
                float2 f3 = __half22float2(*reinterpret_cast<__half2*>(&u0.w));
                acc[0] += v0 * f0.x; acc[1] += v0 * f0.y;
                acc[2] += v0 * f1.x; acc[3] += v0 * f1.y;
                acc[4] += v0 * f2.x; acc[5] += v0 * f2.y;
                acc[6] += v0 * f3.x; acc[7] += v0 * f3.y;
            }
            {
                float2 f0 = __half22float2(*reinterpret_cast<__half2*>(&u1.x));
                float2 f1 = __half22float2(*reinterpret_cast<__half2*>(&u1.y));
                float2 f2 = __half22float2(*reinterpret_cast<__half2*>(&u1.z));
                float2 f3 = __half22float2(*reinterpret_cast<__half2*>(&u1.w));
                acc[0] += v1 * f0.x; acc[1] += v1 * f0.y;
                acc[2] += v1 * f1.x; acc[3] += v1 * f1.y;
                acc[4] += v1 * f2.x; acc[5] += v1 * f2.y;
                acc[6] += v1 * f3.x; acc[7] += v1 * f3.y;
            }
        }
        for (; m < m1; m++) {
            float v = g_values[m];
            int j = __ldg(&j_indices[m]);
            uint4 u = uf[(size_t)j * (BS / 8) + tcol];
            float2 f0 = __half22float2(*reinterpret_cast<__half2*>(&u.x));
            float2 f1 = __half22float2(*reinterpret_cast<__half2*>(&u.y));
            float2 f2 = __half22float2(*reinterpret_cast<__half2*>(&u.z));
            float2 f3 = __half22float2(*reinterpret_cast<__half2*>(&u.w));
            acc[0] += v * f0.x; acc[1] += v * f0.y;
            acc[2] += v * f1.x; acc[3] += v * f1.y;
            acc[4] += v * f2.x; acc[5] += v * f2.y;
            acc[6] += v * f3.x; acc[7] += v * f3.y;
        }

#pragma unroll
        for (int t = 0; t < 8; t++)
            tile[ii][lane * 8 + t] = acc[t];
    }
    __syncthreads();

    // Write out: warp writes one token row per iter (32 consecutive i's = 128B)
    for (int t = warp; t < TT; t += 8) {
        out[(size_t)(tok0 + t) * FDIM + i_base + lane] = tile[lane][t];
    }
}

// ---------------------------------------------------------------------------
// Launch sequence: prep (transposes + rowptr) -> values -> spmm
// ---------------------------------------------------------------------------
extern "C" void kernel_launch(void* const* d_in, const int* in_sizes, int n_in,
                              void* d_out, int out_size) {
    const float* up_facts     = (const float*)d_in[0];   // [B, S, F]
    const float* down_encoder = (const float*)d_in[1];   // [F, D]
    const float* up_decoder   = (const float*)d_in[2];   // [D, F]
    const int*   i_indices    = (const int*)d_in[3];     // [M], sorted, int32
    const int*   j_indices    = (const int*)d_in[4];     // [M], int32
    float*       out          = (float*)d_out;           // [B, S, F]

    __half* udT; cudaGetSymbolAddress((void**)&udT, g_udT);
    __half* ufT; cudaGetSymbolAddress((void**)&ufT, g_ufT);

    // 1) Prep: transpose up_decoder + transpose up_facts + rowptr (one launch)
    {
        int blocks = T1_BLOCKS + T2_BLOCKS + RP_BLOCKS;
        prep_kernel<<<blocks, 256>>>(up_decoder, up_facts, i_indices, udT, ufT);
    }
    // 2) SDDMM values (2 warps per i)
    {
        int threads = 256;
        long long total_threads = (long long)FDIM * 2 * 32;
        int blocks = (int)((total_threads + threads - 1) / threads);
        values_kernel<<<blocks, threads>>>(down_encoder, j_indices);
    }
    // 3) Fused SpMM + output transpose
    {
        dim3 grid(FDIM / TI, BS / TT);
        spmm_fused_kernel<<<grid, 256>>>(j_indices, out);
    }
}